// round 4
// baseline (speedup 1.0000x reference)
#include <cuda_runtime.h>
#include <cuda_fp16.h>
#include <math.h>

#define NB 128
#define NH 256
#define NW 256
#define NC 64
#define CSTR 257   // float2 stride per lane-row in smem tile (conflict-free)

// 128*256*256 complex half = 32 MB static scratch (allocation-free)
__device__ __half2 g_scratch[(size_t)NB * NH * NW];

__device__ __forceinline__ float2 cadd(float2 a, float2 b){ return make_float2(a.x+b.x, a.y+b.y); }
__device__ __forceinline__ float2 csub(float2 a, float2 b){ return make_float2(a.x-b.x, a.y-b.y); }
__device__ __forceinline__ float2 cmul(float2 a, float2 b){
    return make_float2(fmaf(a.x, b.x, -a.y*b.y), fmaf(a.x, b.y, a.y*b.x));
}
// multiply by -i (forward, SIGN=-1) or +i (inverse, SIGN=+1)
template<int SIGN>
__device__ __forceinline__ float2 rot90(float2 a){
    return (SIGN < 0) ? make_float2(a.y, -a.x) : make_float2(-a.y, a.x);
}
// table holds exp(-2*pi*i*j/256); conjugate for inverse
template<int SIGN>
__device__ __forceinline__ float2 twget(const float2* tw, int j){
    float2 w = tw[j];
    return (SIGN < 0) ? w : make_float2(w.x, -w.y);
}

// Fully-unrolled 16-point DFT in registers (radix-4 x2), natural order.
template<int SIGN>
__device__ __forceinline__ void fft16(float2* r, const float2* tw){
    float2 v[16];
#pragma unroll
    for (int p = 0; p < 4; ++p){
        float2 a=r[p], b=r[p+4], c=r[p+8], d=r[p+12];
        float2 t0=cadd(a,c), t1=csub(a,c), t2=cadd(b,d);
        float2 t3=rot90<SIGN>(csub(b,d));
        float2 u0=cadd(t0,t2), u1=cadd(t1,t3), u2=csub(t0,t2), u3=csub(t1,t3);
        if (p){
            u1 = cmul(u1, twget<SIGN>(tw, 16*p));
            u2 = cmul(u2, twget<SIGN>(tw, 32*p));
            u3 = cmul(u3, twget<SIGN>(tw, 48*p));
        }
        v[p]=u0; v[4+p]=u1; v[8+p]=u2; v[12+p]=u3;
    }
#pragma unroll
    for (int m = 0; m < 4; ++m){
        float2 a=v[4*m], b=v[4*m+1], c=v[4*m+2], d=v[4*m+3];
        float2 t0=cadd(a,c), t1=csub(a,c), t2=cadd(b,d);
        float2 t3=rot90<SIGN>(csub(b,d));
        r[m]    = cadd(t0,t2);
        r[4+m]  = cadd(t1,t3);
        r[8+m]  = csub(t0,t2);
        r[12+m] = csub(t1,t3);
    }
}

#define BUILD_TW() do { \
    float sn_, cs_; sincospif(-(float)t * (1.0f/128.0f), &sn_, &cs_); \
    stw[t] = make_float2(cs_, sn_); } while(0)

__device__ __forceinline__ __half2 f2h(float2 v){ return __float22half2_rn(v); }
__device__ __forceinline__ float2 h2f(__half2 v){ return __half22float2(v); }

// ---------------------------------------------------------------------------
// Pass 1: forward FFT along W. 16 rows per block, 256 threads. fp16 store.
// ---------------------------------------------------------------------------
__global__ void __launch_bounds__(256) k_rowfft(const float* __restrict__ x){
    __shared__ float2 s[16*CSTR];
    __shared__ float2 stw[256];
    int t = threadIdx.x;
    BUILD_TW();
    int row0 = blockIdx.x * 16;
    const float* xp = x + (size_t)row0 * NW;
#pragma unroll
    for (int k = 0; k < 16; ++k){
        int idx = t + k*256;
        int rl = idx >> 8, i = idx & 255;
        s[rl*CSTR + i] = make_float2(xp[idx], 0.0f);
    }
    __syncthreads();
    int wl = t & 15, hi = t >> 4;
    float2 r[16];
    float2* srow = s + wl*CSTR;
#pragma unroll
    for (int n2 = 0; n2 < 16; ++n2) r[n2] = srow[16*n2 + hi];
    fft16<-1>(r, stw);
#pragma unroll
    for (int k2 = 1; k2 < 16; ++k2) r[k2] = cmul(r[k2], twget<-1>(stw, k2*hi));
    __syncthreads();
#pragma unroll
    for (int k2 = 0; k2 < 16; ++k2) srow[k2*16 + hi] = r[k2];
    __syncthreads();
#pragma unroll
    for (int i = 0; i < 16; ++i) r[i] = srow[hi*16 + i];
    fft16<-1>(r, stw);
    __syncthreads();
#pragma unroll
    for (int k1 = 0; k1 < 16; ++k1) srow[16*k1 + hi] = r[k1];
    __syncthreads();
    __half2* gp = g_scratch + (size_t)row0 * NW;
#pragma unroll
    for (int k = 0; k < 16; ++k){
        int idx = t + k*256;
        int rl = idx >> 8, i = idx & 255;
        gp[idx] = f2h(s[rl*CSTR + i]);
    }
}

// ---------------------------------------------------------------------------
// Pass 2: forward FFT along H + mask (fftshift folded into index remap) +
// inverse FFT along H (scaled by 1/256), fused. fp16 in/out.
// ---------------------------------------------------------------------------
__global__ void __launch_bounds__(256) k_colfft_mask(const float* __restrict__ pi,
                                                     const int* __restrict__ cid){
    __shared__ float2 s[16*CSTR];
    __shared__ float2 stw[256];
    __shared__ float sPI[NC];
    int t = threadIdx.x;
    BUILD_TW();
    int b  = blockIdx.y;
    int w0 = blockIdx.x * 16;
    if (t < NC) sPI[t] = pi[((b + 64) & 127) * NC + t];
    __half2* g = g_scratch + (size_t)b * NH * NW;
#pragma unroll
    for (int k = 0; k < 16; ++k){
        int idx = t + k*256;
        int h = idx >> 4, w = idx & 15;
        s[w*CSTR + h] = h2f(g[h*NW + w0 + w]);
    }
    __syncthreads();
    int wl = t & 15, hi = t >> 4;
    int wp = (w0 + wl + 128) & 255;
    float2 r[16];
    float2* scol = s + wl*CSTR;
    // forward over h
#pragma unroll
    for (int n2 = 0; n2 < 16; ++n2) r[n2] = scol[16*n2 + hi];
    fft16<-1>(r, stw);
#pragma unroll
    for (int k2 = 1; k2 < 16; ++k2) r[k2] = cmul(r[k2], twget<-1>(stw, k2*hi));
    __syncthreads();
#pragma unroll
    for (int k2 = 0; k2 < 16; ++k2) scol[k2*16 + hi] = r[k2];
    __syncthreads();
#pragma unroll
    for (int i = 0; i < 16; ++i) r[i] = scol[hi*16 + i];
    fft16<-1>(r, stw);
    // mask multiply in registers: h = 16*k1 + hi
#pragma unroll
    for (int k1 = 0; k1 < 16; ++k1){
        int hp = (16*k1 + hi + 128) & 255;
        int c = __ldg(&cid[hp*NW + wp]);
        float m = (c < NC) ? sPI[c] : 1.0f;
        r[k1].x *= m; r[k1].y *= m;
    }
    // inverse over h, with 1/256 normalization folded in (keeps fp16 range)
    fft16<1>(r, stw);
#pragma unroll
    for (int n1 = 1; n1 < 16; ++n1) r[n1] = cmul(r[n1], twget<1>(stw, n1*hi));
    __syncthreads();
#pragma unroll
    for (int n1 = 0; n1 < 16; ++n1) scol[n1*16 + hi] = r[n1];
    __syncthreads();
#pragma unroll
    for (int i = 0; i < 16; ++i) r[i] = scol[hi*16 + i];
    fft16<1>(r, stw);
    const float inv256 = 1.0f / 256.0f;
    __syncthreads();
#pragma unroll
    for (int n2 = 0; n2 < 16; ++n2)
        scol[16*n2 + hi] = make_float2(r[n2].x * inv256, r[n2].y * inv256);
    __syncthreads();
#pragma unroll
    for (int k = 0; k < 16; ++k){
        int idx = t + k*256;
        int h = idx >> 4, w = idx & 15;
        g[h*NW + w0 + w] = f2h(s[w*CSTR + h]);
    }
}

// ---------------------------------------------------------------------------
// Pass 3: inverse FFT along W (remaining 1/256) + magnitude + 3 channels.
// Block 0 additionally appends the pattern_importance passthrough.
// ---------------------------------------------------------------------------
__global__ void __launch_bounds__(256) k_irow_out(const float* __restrict__ x,
                                                  const float* __restrict__ pi,
                                                  float* __restrict__ out){
    __shared__ float2 s[16*CSTR];
    __shared__ float2 stw[256];
    int t = threadIdx.x;
    BUILD_TW();
    int row0 = blockIdx.x * 16;
    const __half2* gp = g_scratch + (size_t)row0 * NW;
#pragma unroll
    for (int k = 0; k < 16; ++k){
        int idx = t + k*256;
        int rl = idx >> 8, i = idx & 255;
        s[rl*CSTR + i] = h2f(gp[idx]);
    }
    __syncthreads();
    int wl = t & 15, hi = t >> 4;
    float2 r[16];
    float2* srow = s + wl*CSTR;
#pragma unroll
    for (int k1 = 0; k1 < 16; ++k1) r[k1] = srow[16*k1 + hi];
    fft16<1>(r, stw);
#pragma unroll
    for (int n1 = 1; n1 < 16; ++n1) r[n1] = cmul(r[n1], twget<1>(stw, n1*hi));
    __syncthreads();
#pragma unroll
    for (int n1 = 0; n1 < 16; ++n1) srow[n1*16 + hi] = r[n1];
    __syncthreads();
#pragma unroll
    for (int i = 0; i < 16; ++i) r[i] = srow[hi*16 + i];
    fft16<1>(r, stw);
    __syncthreads();
#pragma unroll
    for (int n2 = 0; n2 < 16; ++n2) srow[16*n2 + hi] = r[n2];
    __syncthreads();
    const float sc = 1.0f / 256.0f;   // second half of 1/65536
    const float* xp = x + (size_t)row0 * NW;
#pragma unroll
    for (int k = 0; k < 16; ++k){
        int idx = t + k*256;
        int rl = idx >> 8, i = idx & 255;
        int row = row0 + rl;
        int bb = row >> 8, h = row & 255;
        float2 v = s[rl*CSTR + i];
        float mag = sqrtf(fmaf(v.x, v.x, v.y*v.y)) * sc;
        float xv = xp[idx];
        size_t base = ((size_t)(bb*3) * NH + h) * NW + i;
        out[base]                    = xv;
        out[base + (size_t)NH*NW]    = mag;
        out[base + 2*(size_t)NH*NW]  = fabsf(mag - xv);
    }
    if (blockIdx.x == 0){
        for (int i = t; i < NB * NC; i += 256)
            out[(size_t)NB * 3 * NH * NW + i] = pi[i];
    }
}

extern "C" void kernel_launch(void* const* d_in, const int* in_sizes, int n_in,
                              void* d_out, int out_size) {
    const float* x  = (const float*)d_in[0];   // [128,256,256] f32
    const float* pi = (const float*)d_in[1];   // [128,64]      f32
    const int* cid  = (const int*)d_in[2];     // [256,256]     i32
    float* out = (float*)d_out;                // [128,3,256,256] + [128,64]

    k_rowfft<<<(NB*NH)/16, 256>>>(x);
    k_colfft_mask<<<dim3(NW/16, NB), 256>>>(pi, cid);
    k_irow_out<<<(NB*NH)/16, 256>>>(x, pi, out);
}

// round 5
// speedup vs baseline: 1.1397x; 1.1397x over previous
#include <cuda_runtime.h>
#include <math.h>

#define NB 128
#define NH 256
#define NW 256
#define NC 64
#define GS 273    // float2 stride per transpose group (16*17 + 1) — conflict-free

// 128*256*256 complex floats = 64 MB static scratch (allocation-free)
__device__ float2 g_scratch[(size_t)NB * NH * NW];

__device__ __forceinline__ float2 cadd(float2 a, float2 b){ return make_float2(a.x+b.x, a.y+b.y); }
__device__ __forceinline__ float2 csub(float2 a, float2 b){ return make_float2(a.x-b.x, a.y-b.y); }
__device__ __forceinline__ float2 cmul(float2 a, float2 b){
    return make_float2(fmaf(a.x, b.x, -a.y*b.y), fmaf(a.x, b.y, a.y*b.x));
}
template<int SIGN>
__device__ __forceinline__ float2 rot90(float2 a){
    return (SIGN < 0) ? make_float2(a.y, -a.x) : make_float2(-a.y, a.x);
}
// stw[j] = exp(-2*pi*i*j/256); conjugate for inverse
template<int SIGN>
__device__ __forceinline__ float2 twget(const float2* tw, int j){
    float2 w = tw[j];
    return (SIGN < 0) ? w : make_float2(w.x, -w.y);
}

// Fully-unrolled 16-point DFT in registers (radix-4 x2), natural order.
// r_out[k] = sum_n r_in[n] * exp(SIGN*2*pi*i*k*n/16)
template<int SIGN>
__device__ __forceinline__ void fft16(float2* r, const float2* tw){
    float2 v[16];
#pragma unroll
    for (int p = 0; p < 4; ++p){
        float2 a=r[p], b=r[p+4], c=r[p+8], d=r[p+12];
        float2 t0=cadd(a,c), t1=csub(a,c), t2=cadd(b,d);
        float2 t3=rot90<SIGN>(csub(b,d));
        float2 u0=cadd(t0,t2), u1=cadd(t1,t3), u2=csub(t0,t2), u3=csub(t1,t3);
        if (p){
            u1 = cmul(u1, twget<SIGN>(tw, 16*p));
            u2 = cmul(u2, twget<SIGN>(tw, 32*p));
            u3 = cmul(u3, twget<SIGN>(tw, 48*p));
        }
        v[p]=u0; v[4+p]=u1; v[8+p]=u2; v[12+p]=u3;
    }
#pragma unroll
    for (int m = 0; m < 4; ++m){
        float2 a=v[4*m], b=v[4*m+1], c=v[4*m+2], d=v[4*m+3];
        float2 t0=cadd(a,c), t1=csub(a,c), t2=cadd(b,d);
        float2 t3=rot90<SIGN>(csub(b,d));
        r[m]    = cadd(t0,t2);
        r[4+m]  = cadd(t1,t3);
        r[8+m]  = csub(t0,t2);
        r[12+m] = csub(t1,t3);
    }
}

#define BUILD_TW() do { \
    float sn_, cs_; sincospif(-(float)t * (1.0f/128.0f), &sn_, &cs_); \
    stw[t] = make_float2(cs_, sn_); } while(0)

// ---------------------------------------------------------------------------
// Pass 1: forward FFT along W. 16 rows/block, 256 threads.
// thread: n1 = t&15 (intra-row), row group wl = t>>4. Direct coalesced LDG/STG;
// single half-warp smem transpose.
// ---------------------------------------------------------------------------
__global__ void __launch_bounds__(256) k_rowfft(const float* __restrict__ x){
    __shared__ float2 s[16*GS];
    __shared__ float2 stw[256];
    int t = threadIdx.x;
    BUILD_TW();
    __syncthreads();
    int n1 = t & 15, wl = t >> 4;
    int row = blockIdx.x * 16 + wl;
    const float* xr = x + (size_t)row * NW;
    float2 r[16];
#pragma unroll
    for (int n2 = 0; n2 < 16; ++n2) r[n2] = make_float2(xr[n1 + 16*n2], 0.0f);
    fft16<-1>(r, stw);                    // over n2 -> regs k2
#pragma unroll
    for (int k2 = 1; k2 < 16; ++k2) r[k2] = cmul(r[k2], twget<-1>(stw, n1*k2));
    float2* sg = s + wl*GS;
#pragma unroll
    for (int k2 = 0; k2 < 16; ++k2) sg[n1*17 + k2] = r[k2];
    __syncwarp();
#pragma unroll
    for (int i = 0; i < 16; ++i) r[i] = sg[i*17 + n1];   // thread role: k2 = n1
    fft16<-1>(r, stw);                    // over n1 -> regs k1: X[16*k1 + k2]
    float2* gp = g_scratch + (size_t)row * NW;
#pragma unroll
    for (int k1 = 0; k1 < 16; ++k1) gp[n1 + 16*k1] = r[k1];
}

// ---------------------------------------------------------------------------
// Pass 2: fwd FFT along H + mask (fftshift folded) + inv FFT along H, fused.
// Block = (batch b, 16-column tile). thread: w = t&15, u = t>>4 (= n1 role).
// Direct coalesced LDG/STG; two block-wide smem transposes.
// ---------------------------------------------------------------------------
__global__ void __launch_bounds__(256) k_colfft_mask(const float* __restrict__ pi,
                                                     const int* __restrict__ cid){
    __shared__ float2 s[16*GS];
    __shared__ float2 stw[256];
    __shared__ float sPI[NC];
    int t = threadIdx.x;
    BUILD_TW();
    int b  = blockIdx.y;
    int w0 = blockIdx.x * 16;
    if (t < NC) sPI[t] = pi[((b + 64) & 127) * NC + t];
    __syncthreads();
    int w = t & 15, u = t >> 4;
    float2* g = g_scratch + (size_t)b * NH * NW + w0;
    float2 r[16];
#pragma unroll
    for (int n2 = 0; n2 < 16; ++n2) r[n2] = g[(u + 16*n2)*NW + w];
    fft16<-1>(r, stw);                    // over n2 -> k2
#pragma unroll
    for (int k2 = 1; k2 < 16; ++k2) r[k2] = cmul(r[k2], twget<-1>(stw, u*k2));
    float2* sg = s + w*GS;
#pragma unroll
    for (int k2 = 0; k2 < 16; ++k2) sg[u*17 + k2] = r[k2];
    __syncthreads();
#pragma unroll
    for (int i = 0; i < 16; ++i) r[i] = sg[i*17 + u];    // thread role: k2 = u
    fft16<-1>(r, stw);                    // over n1 -> k1: F[16*k1 + k2]
    // mask in registers: h-freq = 16*k1 + u
    int wp = (w0 + w + 128) & 255;
#pragma unroll
    for (int k1 = 0; k1 < 16; ++k1){
        int hp = (16*k1 + u + 128) & 255;
        int c = __ldg(&cid[hp*NW + wp]);
        float m = (c < NC) ? sPI[c] : 1.0f;
        r[k1].x *= m; r[k1].y *= m;
    }
    // inverse over h (unscaled)
    fft16<1>(r, stw);                     // over k1 -> m1
#pragma unroll
    for (int m1 = 1; m1 < 16; ++m1) r[m1] = cmul(r[m1], twget<1>(stw, u*m1));
    __syncthreads();
#pragma unroll
    for (int m1 = 0; m1 < 16; ++m1) sg[u*17 + m1] = r[m1];
    __syncthreads();
#pragma unroll
    for (int i = 0; i < 16; ++i) r[i] = sg[i*17 + u];    // thread role: m1 = u
    fft16<1>(r, stw);                     // over k2 -> m2: y[m1 + 16*m2]
#pragma unroll
    for (int m2 = 0; m2 < 16; ++m2) g[(u + 16*m2)*NW + w] = r[m2];
}

// ---------------------------------------------------------------------------
// Pass 3: inverse FFT along W + magnitude + 3 output channels + pi tail.
// thread: u = t&15 (= k2 role), row group rl = t>>4. Half-warp transpose.
// ---------------------------------------------------------------------------
__global__ void __launch_bounds__(256) k_irow_out(const float* __restrict__ x,
                                                  const float* __restrict__ pi,
                                                  float* __restrict__ out){
    __shared__ float2 s[16*GS];
    __shared__ float2 stw[256];
    int t = threadIdx.x;
    BUILD_TW();
    __syncthreads();
    int u = t & 15, rl = t >> 4;
    int row = blockIdx.x * 16 + rl;
    int b = row >> 8, h = row & 255;
    const float2* gp = g_scratch + (size_t)row * NW;
    float2 r[16];
#pragma unroll
    for (int k1 = 0; k1 < 16; ++k1) r[k1] = gp[u + 16*k1];
    fft16<1>(r, stw);                     // over k1 -> m1
#pragma unroll
    for (int m1 = 1; m1 < 16; ++m1) r[m1] = cmul(r[m1], twget<1>(stw, u*m1));
    float2* sg = s + rl*GS;
#pragma unroll
    for (int m1 = 0; m1 < 16; ++m1) sg[u*17 + m1] = r[m1];
    __syncwarp();
#pragma unroll
    for (int i = 0; i < 16; ++i) r[i] = sg[i*17 + u];    // thread role: m1 = u
    fft16<1>(r, stw);                     // over k2 -> m2: y[m1 + 16*m2]
    const float sc = 1.0f / 65536.0f;
    const float* xr = x + (size_t)row * NW;
    size_t base = ((size_t)(b*3) * NH + h) * NW;
#pragma unroll
    for (int m2 = 0; m2 < 16; ++m2){
        int m = u + 16*m2;
        float2 v = r[m2];
        float mag = sqrtf(fmaf(v.x, v.x, v.y*v.y)) * sc;
        float xv = xr[m];
        out[base + m]                      = xv;
        out[base + (size_t)NH*NW + m]      = mag;
        out[base + 2*(size_t)NH*NW + m]    = fabsf(mag - xv);
    }
    if (blockIdx.x == 0){
        for (int i = t; i < NB * NC; i += 256)
            out[(size_t)NB * 3 * NH * NW + i] = pi[i];
    }
}

extern "C" void kernel_launch(void* const* d_in, const int* in_sizes, int n_in,
                              void* d_out, int out_size) {
    const float* x  = (const float*)d_in[0];   // [128,256,256] f32
    const float* pi = (const float*)d_in[1];   // [128,64]      f32
    const int* cid  = (const int*)d_in[2];     // [256,256]     i32
    float* out = (float*)d_out;                // [128,3,256,256] + [128,64]

    k_rowfft<<<(NB*NH)/16, 256>>>(x);
    k_colfft_mask<<<dim3(NW/16, NB), 256>>>(pi, cid);
    k_irow_out<<<(NB*NH)/16, 256>>>(x, pi, out);
}

// round 7
// speedup vs baseline: 1.7936x; 1.5738x over previous
#include <cuda_runtime.h>
#include <math.h>

#define NB 128
#define NH 256
#define NW 256
#define NC 64
#define GS 273    // float2 stride per transpose group (16*17 + 1) — conflict-free

// 128*256*256 complex floats = 64 MB static scratch (allocation-free)
__device__ float2 g_scratch[(size_t)NB * NH * NW];

__device__ __forceinline__ float2 cadd(float2 a, float2 b){ return make_float2(a.x+b.x, a.y+b.y); }
__device__ __forceinline__ float2 csub(float2 a, float2 b){ return make_float2(a.x-b.x, a.y-b.y); }
__device__ __forceinline__ float2 cmul(float2 a, float2 b){
    return make_float2(fmaf(a.x, b.x, -a.y*b.y), fmaf(a.x, b.y, a.y*b.x));
}
template<int SIGN>
__device__ __forceinline__ float2 rot90(float2 a){   // × (-i) fwd, (+i) inv
    return (SIGN < 0) ? make_float2(a.y, -a.x) : make_float2(-a.y, a.x);
}
// multiply by constant twiddle given FORWARD components (wr, wi); conj for inverse
template<int SIGN>
__device__ __forceinline__ float2 cmulw(float2 a, float wr, float wi_f){
    float wi = (SIGN < 0) ? wi_f : -wi_f;
    return make_float2(fmaf(a.x, wr, -a.y*wi), fmaf(a.x, wi, a.y*wr));
}

// Fully-unrolled 16-point DFT in registers, all twiddles as immediates.
template<int SIGN>
__device__ __forceinline__ void fft16(float2* r){
    const float C1 = 0.92387953251f, S1 = 0.38268343236f, C2 = 0.70710678119f;
    float2 v[16];
#pragma unroll
    for (int p = 0; p < 4; ++p){
        float2 a=r[p], b=r[p+4], c=r[p+8], d=r[p+12];
        float2 t0=cadd(a,c), t1=csub(a,c), t2=cadd(b,d);
        float2 t3=rot90<SIGN>(csub(b,d));
        float2 u0=cadd(t0,t2), u1=cadd(t1,t3), u2=csub(t0,t2), u3=csub(t1,t3);
        if (p == 1){
            u1 = cmulw<SIGN>(u1,  C1, -S1);
            u2 = cmulw<SIGN>(u2,  C2, -C2);
            u3 = cmulw<SIGN>(u3,  S1, -C1);
        } else if (p == 2){
            u1 = cmulw<SIGN>(u1,  C2, -C2);
            u2 = rot90<SIGN>(u2);
            u3 = cmulw<SIGN>(u3, -C2, -C2);
        } else if (p == 3){
            u1 = cmulw<SIGN>(u1,  S1, -C1);
            u2 = cmulw<SIGN>(u2, -C2, -C2);
            u3 = cmulw<SIGN>(u3, -C1,  S1);
        }
        v[p]=u0; v[4+p]=u1; v[8+p]=u2; v[12+p]=u3;
    }
#pragma unroll
    for (int m = 0; m < 4; ++m){
        float2 a=v[4*m], b=v[4*m+1], c=v[4*m+2], d=v[4*m+3];
        float2 t0=cadd(a,c), t1=csub(a,c), t2=cadd(b,d);
        float2 t3=rot90<SIGN>(csub(b,d));
        r[m]    = cadd(t0,t2);
        r[4+m]  = cadd(t1,t3);
        r[8+m]  = csub(t0,t2);
        r[12+m] = csub(t1,t3);
    }
}

// Apply r[k] *= w^k for w = exp(SIGN*2*pi*i*n1/256), k=1..15, via power chain.
template<int SIGN>
__device__ __forceinline__ void twiddle_pows(float2* r, int n1){
    float sn, cs;
    sincospif((float)n1 * (1.0f/128.0f), &sn, &cs);
    float2 w = make_float2(cs, (SIGN < 0) ? -sn : sn);
    float2 acc = w;
    r[1] = cmul(r[1], acc);
#pragma unroll
    for (int k = 2; k < 16; ++k){
        acc = cmul(acc, w);
        r[k] = cmul(r[k], acc);
    }
}

// ---------------------------------------------------------------------------
// Pass 1: forward FFT along W. 16 rows/block, 256 threads. No block barriers.
// ---------------------------------------------------------------------------
__global__ void __launch_bounds__(256) k_rowfft(const float* __restrict__ x){
    __shared__ float2 s[16*GS];
    int t = threadIdx.x;
    int n1 = t & 15, wl = t >> 4;
    int row = blockIdx.x * 16 + wl;
    const float* xr = x + (size_t)row * NW;
    float2 r[16];
#pragma unroll
    for (int n2 = 0; n2 < 16; ++n2) r[n2] = make_float2(xr[n1 + 16*n2], 0.0f);
    fft16<-1>(r);                         // over n2 -> regs k2
    twiddle_pows<-1>(r, n1);
    float2* sg = s + wl*GS;
#pragma unroll
    for (int k2 = 0; k2 < 16; ++k2) sg[n1*17 + k2] = r[k2];
    __syncwarp();
#pragma unroll
    for (int i = 0; i < 16; ++i) r[i] = sg[i*17 + n1];   // thread role: k2 = n1
    fft16<-1>(r);                         // over n1 -> regs k1: X[16*k1 + k2]
    float2* gp = g_scratch + (size_t)row * NW;
#pragma unroll
    for (int k1 = 0; k1 < 16; ++k1) gp[n1 + 16*k1] = r[k1];
}

// ---------------------------------------------------------------------------
// Pass 2: fwd FFT along H + mask (fftshift folded) + inv FFT along H, fused.
// Block = (batch b, 16-column tile). thread: w = t&15, u = t>>4.
// ---------------------------------------------------------------------------
__global__ void __launch_bounds__(256) k_colfft_mask(const float* __restrict__ pi,
                                                     const int* __restrict__ cid){
    __shared__ float2 s[16*GS];
    __shared__ float sPI[NC];
    int t = threadIdx.x;
    int b  = blockIdx.y;
    int w0 = blockIdx.x * 16;
    if (t < NC) sPI[t] = pi[((b + 64) & 127) * NC + t];
    int w = t & 15, u = t >> 4;
    float2* g = g_scratch + (size_t)b * NH * NW + w0;
    float2 r[16];
#pragma unroll
    for (int n2 = 0; n2 < 16; ++n2) r[n2] = g[(u + 16*n2)*NW + w];
    fft16<-1>(r);                         // over n2 -> k2
    twiddle_pows<-1>(r, u);
    float2* sg = s + w*GS;
#pragma unroll
    for (int k2 = 0; k2 < 16; ++k2) sg[u*17 + k2] = r[k2];
    __syncthreads();                      // also covers sPI writes
#pragma unroll
    for (int i = 0; i < 16; ++i) r[i] = sg[i*17 + u];    // thread role: k2 = u
    fft16<-1>(r);                         // over n1 -> k1: F[16*k1 + k2]
    // mask in registers: h-freq = 16*k1 + u
    int wp = (w0 + w + 128) & 255;
#pragma unroll
    for (int k1 = 0; k1 < 16; ++k1){
        int hp = (16*k1 + u + 128) & 255;
        int c = __ldg(&cid[hp*NW + wp]);
        float m = (c < NC) ? sPI[c] : 1.0f;
        r[k1].x *= m; r[k1].y *= m;
    }
    // inverse over h (unscaled)
    fft16<1>(r);                          // over k1 -> m1
    twiddle_pows<1>(r, u);
    __syncthreads();
#pragma unroll
    for (int m1 = 0; m1 < 16; ++m1) sg[u*17 + m1] = r[m1];
    __syncthreads();
#pragma unroll
    for (int i = 0; i < 16; ++i) r[i] = sg[i*17 + u];    // thread role: m1 = u
    fft16<1>(r);                          // over k2 -> m2: y[m1 + 16*m2]
#pragma unroll
    for (int m2 = 0; m2 < 16; ++m2) g[(u + 16*m2)*NW + w] = r[m2];
}

// ---------------------------------------------------------------------------
// Pass 3: inverse FFT along W + magnitude + 3 output channels + pi tail.
// ---------------------------------------------------------------------------
__global__ void __launch_bounds__(256) k_irow_out(const float* __restrict__ x,
                                                  const float* __restrict__ pi,
                                                  float* __restrict__ out){
    __shared__ float2 s[16*GS];
    int t = threadIdx.x;
    int u = t & 15, rl = t >> 4;
    int row = blockIdx.x * 16 + rl;
    int b = row >> 8, h = row & 255;
    const float2* gp = g_scratch + (size_t)row * NW;
    float2 r[16];
#pragma unroll
    for (int k1 = 0; k1 < 16; ++k1) r[k1] = gp[u + 16*k1];
    fft16<1>(r);                          // over k1 -> m1
    twiddle_pows<1>(r, u);
    float2* sg = s + rl*GS;
#pragma unroll
    for (int m1 = 0; m1 < 16; ++m1) sg[u*17 + m1] = r[m1];
    __syncwarp();
#pragma unroll
    for (int i = 0; i < 16; ++i) r[i] = sg[i*17 + u];    // thread role: m1 = u
    fft16<1>(r);                          // over k2 -> m2: y[m1 + 16*m2]
    const float sc = 1.0f / 65536.0f;
    const float* xr = x + (size_t)row * NW;
    size_t base = ((size_t)(b*3) * NH + h) * NW;
#pragma unroll
    for (int m2 = 0; m2 < 16; ++m2){
        int m = u + 16*m2;
        float2 v = r[m2];
        float mag = sqrtf(fmaf(v.x, v.x, v.y*v.y)) * sc;
        float xv = xr[m];
        out[base + m]                      = xv;
        out[base + (size_t)NH*NW + m]      = mag;
        out[base + 2*(size_t)NH*NW + m]    = fabsf(mag - xv);
    }
    if (blockIdx.x == 0){
        for (int i = t; i < NB * NC; i += 256)
            out[(size_t)NB * 3 * NH * NW + i] = pi[i];
    }
}

extern "C" void kernel_launch(void* const* d_in, const int* in_sizes, int n_in,
                              void* d_out, int out_size) {
    const float* x  = (const float*)d_in[0];   // [128,256,256] f32
    const float* pi = (const float*)d_in[1];   // [128,64]      f32
    const int* cid  = (const int*)d_in[2];     // [256,256]     i32
    float* out = (float*)d_out;                // [128,3,256,256] + [128,64]

    k_rowfft<<<(NB*NH)/16, 256>>>(x);
    k_colfft_mask<<<dim3(NW/16, NB), 256>>>(pi, cid);
    k_irow_out<<<(NB*NH)/16, 256>>>(x, pi, out);
}

// round 8
// speedup vs baseline: 2.0290x; 1.1313x over previous
#include <cuda_runtime.h>
#include <cuda_fp16.h>
#include <math.h>

#define NB 128
#define NH 256
#define NW 256
#define NC 64
#define GS 273    // float2 stride per transpose group (16*17 + 1) — conflict-free

// 128*256*256 complex half = 32 MB static scratch (allocation-free)
__device__ __half2 g_scratch[(size_t)NB * NH * NW];

__device__ __forceinline__ float2 cadd(float2 a, float2 b){ return make_float2(a.x+b.x, a.y+b.y); }
__device__ __forceinline__ float2 csub(float2 a, float2 b){ return make_float2(a.x-b.x, a.y-b.y); }
__device__ __forceinline__ float2 cmul(float2 a, float2 b){
    return make_float2(fmaf(a.x, b.x, -a.y*b.y), fmaf(a.x, b.y, a.y*b.x));
}
template<int SIGN>
__device__ __forceinline__ float2 rot90(float2 a){   // × (-i) fwd, (+i) inv
    return (SIGN < 0) ? make_float2(a.y, -a.x) : make_float2(-a.y, a.x);
}
// multiply by constant twiddle given FORWARD components (wr, wi); conj for inverse
template<int SIGN>
__device__ __forceinline__ float2 cmulw(float2 a, float wr, float wi_f){
    float wi = (SIGN < 0) ? wi_f : -wi_f;
    return make_float2(fmaf(a.x, wr, -a.y*wi), fmaf(a.x, wi, a.y*wr));
}
__device__ __forceinline__ __half2 f2h(float2 v){ return __float22half2_rn(v); }
__device__ __forceinline__ float2 h2f(__half2 v){ return __half22float2(v); }

// Fully-unrolled 16-point DFT in registers, all twiddles as immediates.
template<int SIGN>
__device__ __forceinline__ void fft16(float2* r){
    const float C1 = 0.92387953251f, S1 = 0.38268343236f, C2 = 0.70710678119f;
    float2 v[16];
#pragma unroll
    for (int p = 0; p < 4; ++p){
        float2 a=r[p], b=r[p+4], c=r[p+8], d=r[p+12];
        float2 t0=cadd(a,c), t1=csub(a,c), t2=cadd(b,d);
        float2 t3=rot90<SIGN>(csub(b,d));
        float2 u0=cadd(t0,t2), u1=cadd(t1,t3), u2=csub(t0,t2), u3=csub(t1,t3);
        if (p == 1){
            u1 = cmulw<SIGN>(u1,  C1, -S1);
            u2 = cmulw<SIGN>(u2,  C2, -C2);
            u3 = cmulw<SIGN>(u3,  S1, -C1);
        } else if (p == 2){
            u1 = cmulw<SIGN>(u1,  C2, -C2);
            u2 = rot90<SIGN>(u2);
            u3 = cmulw<SIGN>(u3, -C2, -C2);
        } else if (p == 3){
            u1 = cmulw<SIGN>(u1,  S1, -C1);
            u2 = cmulw<SIGN>(u2, -C2, -C2);
            u3 = cmulw<SIGN>(u3, -C1,  S1);
        }
        v[p]=u0; v[4+p]=u1; v[8+p]=u2; v[12+p]=u3;
    }
#pragma unroll
    for (int m = 0; m < 4; ++m){
        float2 a=v[4*m], b=v[4*m+1], c=v[4*m+2], d=v[4*m+3];
        float2 t0=cadd(a,c), t1=csub(a,c), t2=cadd(b,d);
        float2 t3=rot90<SIGN>(csub(b,d));
        r[m]    = cadd(t0,t2);
        r[4+m]  = cadd(t1,t3);
        r[8+m]  = csub(t0,t2);
        r[12+m] = csub(t1,t3);
    }
}

// Apply r[k] *= w^k for w = exp(SIGN*2*pi*i*n1/256), k=1..15, via power chain.
template<int SIGN>
__device__ __forceinline__ void twiddle_pows(float2* r, int n1){
    float sn, cs;
    sincospif((float)n1 * (1.0f/128.0f), &sn, &cs);
    float2 w = make_float2(cs, (SIGN < 0) ? -sn : sn);
    float2 acc = w;
    r[1] = cmul(r[1], acc);
#pragma unroll
    for (int k = 2; k < 16; ++k){
        acc = cmul(acc, w);
        r[k] = cmul(r[k], acc);
    }
}

// ---------------------------------------------------------------------------
// Pass 1: forward FFT along W. 16 rows/block, 256 threads. No block barriers.
// ---------------------------------------------------------------------------
__global__ void __launch_bounds__(256) k_rowfft(const float* __restrict__ x){
    __shared__ float2 s[16*GS];
    int t = threadIdx.x;
    int n1 = t & 15, wl = t >> 4;
    int row = blockIdx.x * 16 + wl;
    const float* xr = x + (size_t)row * NW;
    float2 r[16];
#pragma unroll
    for (int n2 = 0; n2 < 16; ++n2) r[n2] = make_float2(xr[n1 + 16*n2], 0.0f);
    fft16<-1>(r);                         // over n2 -> regs k2
    twiddle_pows<-1>(r, n1);
    float2* sg = s + wl*GS;
#pragma unroll
    for (int k2 = 0; k2 < 16; ++k2) sg[n1*17 + k2] = r[k2];
    __syncwarp();
#pragma unroll
    for (int i = 0; i < 16; ++i) r[i] = sg[i*17 + n1];   // thread role: k2 = n1
    fft16<-1>(r);                         // over n1 -> regs k1: X[16*k1 + k2]
    __half2* gp = g_scratch + (size_t)row * NW;
#pragma unroll
    for (int k1 = 0; k1 < 16; ++k1) gp[n1 + 16*k1] = f2h(r[k1]);
}

// ---------------------------------------------------------------------------
// Pass 2: fwd FFT along H + mask (fftshift folded) + inv FFT along H (×1/256),
// fused. Block = (batch b, 16-column tile). thread: w = t&15, u = t>>4.
// ---------------------------------------------------------------------------
__global__ void __launch_bounds__(256) k_colfft_mask(const float* __restrict__ pi,
                                                     const int* __restrict__ cid){
    __shared__ float2 s[16*GS];
    __shared__ float sPI[NC];
    int t = threadIdx.x;
    int b  = blockIdx.y;
    int w0 = blockIdx.x * 16;
    if (t < NC) sPI[t] = pi[((b + 64) & 127) * NC + t];
    int w = t & 15, u = t >> 4;
    __half2* g = g_scratch + (size_t)b * NH * NW + w0;
    float2 r[16];
#pragma unroll
    for (int n2 = 0; n2 < 16; ++n2) r[n2] = h2f(g[(u + 16*n2)*NW + w]);
    // hoist cid loads: issue alongside the scratch loads, consumed after T1
    int wp = (w0 + w + 128) & 255;
    int cc[16];
#pragma unroll
    for (int k1 = 0; k1 < 16; ++k1){
        int hp = (16*k1 + u + 128) & 255;
        cc[k1] = __ldg(&cid[hp*NW + wp]);
    }
    fft16<-1>(r);                         // over n2 -> k2
    twiddle_pows<-1>(r, u);
    float2* sg = s + w*GS;
#pragma unroll
    for (int k2 = 0; k2 < 16; ++k2) sg[u*17 + k2] = r[k2];
    __syncthreads();                      // also covers sPI writes
#pragma unroll
    for (int i = 0; i < 16; ++i) r[i] = sg[i*17 + u];    // thread role: k2 = u
    fft16<-1>(r);                         // over n1 -> k1: F[16*k1 + k2]
    // mask in registers: h-freq = 16*k1 + u
#pragma unroll
    for (int k1 = 0; k1 < 16; ++k1){
        float m = (cc[k1] < NC) ? sPI[cc[k1]] : 1.0f;
        r[k1].x *= m; r[k1].y *= m;
    }
    // inverse over h (scaled by 1/256 at store to keep fp16 range)
    fft16<1>(r);                          // over k1 -> m1
    twiddle_pows<1>(r, u);
    __syncthreads();
#pragma unroll
    for (int m1 = 0; m1 < 16; ++m1) sg[u*17 + m1] = r[m1];
    __syncthreads();
#pragma unroll
    for (int i = 0; i < 16; ++i) r[i] = sg[i*17 + u];    // thread role: m1 = u
    fft16<1>(r);                          // over k2 -> m2: y[m1 + 16*m2]
    const float inv256 = 1.0f / 256.0f;
#pragma unroll
    for (int m2 = 0; m2 < 16; ++m2)
        g[(u + 16*m2)*NW + w] = f2h(make_float2(r[m2].x * inv256, r[m2].y * inv256));
}

// ---------------------------------------------------------------------------
// Pass 3: inverse FFT along W (remaining 1/256) + magnitude + 3 channels + pi.
// ---------------------------------------------------------------------------
__global__ void __launch_bounds__(256) k_irow_out(const float* __restrict__ x,
                                                  const float* __restrict__ pi,
                                                  float* __restrict__ out){
    __shared__ float2 s[16*GS];
    int t = threadIdx.x;
    int u = t & 15, rl = t >> 4;
    int row = blockIdx.x * 16 + rl;
    int b = row >> 8, h = row & 255;
    const __half2* gp = g_scratch + (size_t)row * NW;
    float2 r[16];
#pragma unroll
    for (int k1 = 0; k1 < 16; ++k1) r[k1] = h2f(gp[u + 16*k1]);
    fft16<1>(r);                          // over k1 -> m1
    twiddle_pows<1>(r, u);
    float2* sg = s + rl*GS;
#pragma unroll
    for (int m1 = 0; m1 < 16; ++m1) sg[u*17 + m1] = r[m1];
    __syncwarp();
#pragma unroll
    for (int i = 0; i < 16; ++i) r[i] = sg[i*17 + u];    // thread role: m1 = u
    fft16<1>(r);                          // over k2 -> m2: y[m1 + 16*m2]
    const float sc = 1.0f / 256.0f;       // second half of 1/65536
    const float* xr = x + (size_t)row * NW;
    size_t base = ((size_t)(b*3) * NH + h) * NW;
#pragma unroll
    for (int m2 = 0; m2 < 16; ++m2){
        int m = u + 16*m2;
        float2 v = r[m2];
        float mag = sqrtf(fmaf(v.x, v.x, v.y*v.y)) * sc;
        float xv = xr[m];
        out[base + m]                      = xv;
        out[base + (size_t)NH*NW + m]      = mag;
        out[base + 2*(size_t)NH*NW + m]    = fabsf(mag - xv);
    }
    if (blockIdx.x == 0){
        for (int i = t; i < NB * NC; i += 256)
            out[(size_t)NB * 3 * NH * NW + i] = pi[i];
    }
}

extern "C" void kernel_launch(void* const* d_in, const int* in_sizes, int n_in,
                              void* d_out, int out_size) {
    const float* x  = (const float*)d_in[0];   // [128,256,256] f32
    const float* pi = (const float*)d_in[1];   // [128,64]      f32
    const int* cid  = (const int*)d_in[2];     // [256,256]     i32
    float* out = (float*)d_out;                // [128,3,256,256] + [128,64]

    k_rowfft<<<(NB*NH)/16, 256>>>(x);
    k_colfft_mask<<<dim3(NW/16, NB), 256>>>(pi, cid);
    k_irow_out<<<(NB*NH)/16, 256>>>(x, pi, out);
}